// round 5
// baseline (speedup 1.0000x reference)
#include <cuda_runtime.h>

// Problem constants
#define B_    4
#define T_    16
#define C_    256
#define H_    64
#define W_    64
#define HEADS 8
#define DH    32          // head dim
#define NSEQ  (B_*T_*H_)  // 4096 sequences, each of length W_=64
#define NTOK  (NSEQ*W_)   // 262144 tokens
#define SCALE 0.17677669529663689f  // 1/sqrt(32)

// Scratch: __device__ globals are the sanctioned no-alloc scratch mechanism.
// These are uninitialized -> .nv.global bss (no binary bloat).
// g_q is reused for the attention output (each thread consumes its own q row
// into registers before overwriting it; k/v are read via SMEM copies).
__device__ float g_q[(size_t)NTOK * C_];
__device__ float g_k[(size_t)NTOK * C_];
__device__ float g_v[(size_t)NTOK * C_];

// ---------------------------------------------------------------------------
// Kernel 1: fused gather + QKV GEMM.
//   token r = bt*4096 + (h*64 + w);  A[r, c] = x[(bt*C + c)*4096 + (r&4095)]
//   qkv[r, j] = sum_c A[r,c] * w_qkv[c, j] + b_qkv[j],  j in [0, 768)
//   Routed to g_q / g_k / g_v by j/256.
// Tiling: BM=128, BN=128, BK=8, 256 threads, 8x8 micro-tile per thread.
// ---------------------------------------------------------------------------
#define BM 128
#define BN 128
#define BK 8

__global__ __launch_bounds__(256) void qkv_kernel(
    const float* __restrict__ x,
    const float* __restrict__ w,      // [256, 768]
    const float* __restrict__ bias)   // [768]
{
    __shared__ float As[BK][BM];
    __shared__ float Bs[BK][BN];

    const int tid     = threadIdx.x;
    const int rowBase = blockIdx.x * BM;   // token row base (multiple of 128)
    const int colBase = blockIdx.y * BN;   // output col base (0..640 step 128)

    const int bt   = rowBase >> 12;        // 4096 tokens per (b,t); tiles aligned
    const int rem0 = rowBase & 4095;

    // A load mapping: 8 channels x 128 rows, float4 along rows (coalesced)
    const int a_c = tid >> 5;              // 0..7
    const int a_r = (tid & 31) << 2;       // 0..124
    const float* aSrc = x + ((size_t)(bt * C_ + a_c) << 12) + rem0 + a_r;

    // B load mapping: 8 rows (c) x 128 cols, float4 along cols
    const int b_c = tid >> 5;
    const int b_j = (tid & 31) << 2;
    const float* bSrc = w + (size_t)b_c * 768 + colBase + b_j;

    const int ty = tid >> 4, tx = tid & 15;
    const int m0 = ty * 8,   n0 = tx * 8;

    float acc[8][8];
    #pragma unroll
    for (int mi = 0; mi < 8; mi++)
        #pragma unroll
        for (int ni = 0; ni < 8; ni++) acc[mi][ni] = 0.f;

    for (int k0 = 0; k0 < C_; k0 += BK) {
        float4 av = *(const float4*)aSrc;  aSrc += (size_t)BK << 12;  // c += 8
        float4 bv = *(const float4*)bSrc;  bSrc += BK * 768;
        __syncthreads();                    // prev compute done
        *(float4*)&As[a_c][a_r] = av;
        *(float4*)&Bs[b_c][b_j] = bv;
        __syncthreads();                    // tiles visible

        #pragma unroll
        for (int kk = 0; kk < BK; kk++) {
            float a[8], b[8];
            *(float4*)&a[0] = *(const float4*)&As[kk][m0];
            *(float4*)&a[4] = *(const float4*)&As[kk][m0 + 4];
            *(float4*)&b[0] = *(const float4*)&Bs[kk][n0];
            *(float4*)&b[4] = *(const float4*)&Bs[kk][n0 + 4];
            #pragma unroll
            for (int mi = 0; mi < 8; mi++)
                #pragma unroll
                for (int ni = 0; ni < 8; ni++)
                    acc[mi][ni] = fmaf(a[mi], b[ni], acc[mi][ni]);
        }
    }

    // Epilogue: route to q/k/v (tile lies fully in one part since 128 | 256)
    const int part = colBase >> 8;                  // 0=q, 1=k, 2=v
    float* dst = (part == 0) ? g_q : (part == 1) ? g_k : g_v;
    const int jl0 = (colBase & 255) + n0;

    #pragma unroll
    for (int mi = 0; mi < 8; mi++) {
        const size_t rofs = (size_t)(rowBase + m0 + mi) * C_;
        #pragma unroll
        for (int ni = 0; ni < 8; ni++) {
            dst[rofs + jl0 + ni] = acc[mi][ni] + bias[colBase + n0 + ni];
        }
    }
}

// ---------------------------------------------------------------------------
// Kernel 2: attention per (sequence, head-pair). 128 threads = 2 heads x 64 rows.
// k,v tiles in SMEM (broadcast reads); q row, scores, and output all live in
// registers (fully unrolled over L=64). Static SMEM only (32 KB). Output is
// written back in place into g_q.
// ---------------------------------------------------------------------------
__global__ __launch_bounds__(128) void attn_kernel(const float* __restrict__ rb)
{
    __shared__ float ksm[2 * 64 * DH];   // 16 KB
    __shared__ float vsm[2 * 64 * DH];   // 16 KB

    const int tid  = threadIdx.x;
    const int n    = blockIdx.x;          // sequence 0..4095
    const int hp   = blockIdx.y;          // head pair 0..3
    const int hsub = tid >> 6;            // 0/1
    const int i    = tid & 63;            // query row
    const int h    = hp * 2 + hsub;

    const size_t base = (size_t)n * 64 * C_;

    // Cooperative float4 load of k, v for both heads (coalesced)
    #pragma unroll
    for (int it = 0; it < 8; it++) {
        int e   = tid + 128 * it;         // float4 index 0..1023
        int hs  = e >> 9;
        int row = (e >> 3) & 63;
        int d4  = (e & 7) << 2;
        int hh  = hp * 2 + hs;
        size_t g = base + (size_t)row * C_ + hh * DH + d4;
        ((float4*)ksm)[e] = *(const float4*)&g_k[g];
        ((float4*)vsm)[e] = *(const float4*)&g_v[g];
    }

    // q row -> registers
    float qv[DH];
    const size_t qbase = base + (size_t)i * C_ + h * DH;
    #pragma unroll
    for (int d = 0; d < DH; d += 4) {
        float4 t = *(const float4*)&g_q[qbase + d];
        qv[d] = t.x; qv[d+1] = t.y; qv[d+2] = t.z; qv[d+3] = t.w;
    }
    __syncthreads();

    // Scores in registers: s[j] = scale * q.k_j + bias[h,i,j]
    const float* brow  = rb + (size_t)h * 4096 + i * 64;
    const float* kbase = ksm + hsub * (64 * DH);
    float s[64];
    float m = -1e30f;
    #pragma unroll
    for (int j = 0; j < 64; j++) {
        const float* krow = kbase + j * DH;
        float d0 = 0.f, d1 = 0.f, d2 = 0.f, d3 = 0.f;
        #pragma unroll
        for (int d = 0; d < DH; d += 4) {
            float4 kvv = *(const float4*)&krow[d];
            d0 = fmaf(qv[d],   kvv.x, d0);
            d1 = fmaf(qv[d+1], kvv.y, d1);
            d2 = fmaf(qv[d+2], kvv.z, d2);
            d3 = fmaf(qv[d+3], kvv.w, d3);
        }
        float sc = fmaf((d0 + d1) + (d2 + d3), SCALE, brow[j]);
        s[j] = sc;
        m = fmaxf(m, sc);
    }

    // Softmax (registers only)
    float sum = 0.f;
    #pragma unroll
    for (int j = 0; j < 64; j++) {
        float e = __expf(s[j] - m);
        s[j] = e;
        sum += e;
    }
    const float inv = 1.f / sum;

    // O = P V
    float o[DH];
    #pragma unroll
    for (int d = 0; d < DH; d++) o[d] = 0.f;
    const float* vbase = vsm + hsub * (64 * DH);
    #pragma unroll
    for (int j = 0; j < 64; j++) {
        float p = s[j] * inv;
        const float* vrow = vbase + j * DH;
        #pragma unroll
        for (int d = 0; d < DH; d += 4) {
            float4 vv = *(const float4*)&vrow[d];
            o[d]   = fmaf(p, vv.x, o[d]);
            o[d+1] = fmaf(p, vv.y, o[d+1]);
            o[d+2] = fmaf(p, vv.z, o[d+2]);
            o[d+3] = fmaf(p, vv.w, o[d+3]);
        }
    }

    // Write output in place over q (this thread's own q row, already consumed)
    #pragma unroll
    for (int d = 0; d < DH; d += 4) {
        float4 t; t.x = o[d]; t.y = o[d+1]; t.z = o[d+2]; t.w = o[d+3];
        *(float4*)&g_q[qbase + d] = t;
    }
}

// ---------------------------------------------------------------------------
// Kernel 3: output projection + scatter back to [B,T,C,H,W].
//   out[r, c_out] = sum_c o[r,c] * w_proj[c, c_out] + b_proj[c_out]
// A = g_q (attention output), row-major [NTOK, 256]; loaded transposed to SMEM.
// ---------------------------------------------------------------------------
__global__ __launch_bounds__(256) void proj_kernel(
    const float* __restrict__ w,      // [256, 256]
    const float* __restrict__ bias,   // [256]
    float* __restrict__ out)
{
    __shared__ float As[BK][BM];
    __shared__ float Bs[BK][BN];

    const int tid     = threadIdx.x;
    const int rowBase = blockIdx.x * BM;
    const int colBase = blockIdx.y * BN;

    // A load: thread reads float4 along channels, stores transposed
    const int a_r  = tid >> 1;             // 0..127
    const int a_c4 = (tid & 1) << 2;       // 0 or 4
    const float* aSrc = g_q + (size_t)(rowBase + a_r) * C_ + a_c4;

    const int b_c = tid >> 5;
    const int b_j = (tid & 31) << 2;
    const float* bSrc = w + (size_t)b_c * C_ + colBase + b_j;

    const int ty = tid >> 4, tx = tid & 15;
    const int m0 = ty * 8,   n0 = tx * 8;

    float acc[8][8];
    #pragma unroll
    for (int mi = 0; mi < 8; mi++)
        #pragma unroll
        for (int ni = 0; ni < 8; ni++) acc[mi][ni] = 0.f;

    for (int k0 = 0; k0 < C_; k0 += BK) {
        float4 av = *(const float4*)aSrc;  aSrc += BK;
        float4 bv = *(const float4*)bSrc;  bSrc += BK * C_;
        __syncthreads();
        As[a_c4 + 0][a_r] = av.x;
        As[a_c4 + 1][a_r] = av.y;
        As[a_c4 + 2][a_r] = av.z;
        As[a_c4 + 3][a_r] = av.w;
        *(float4*)&Bs[b_c][b_j] = bv;
        __syncthreads();

        #pragma unroll
        for (int kk = 0; kk < BK; kk++) {
            float a[8], b[8];
            *(float4*)&a[0] = *(const float4*)&As[kk][m0];
            *(float4*)&a[4] = *(const float4*)&As[kk][m0 + 4];
            *(float4*)&b[0] = *(const float4*)&Bs[kk][n0];
            *(float4*)&b[4] = *(const float4*)&Bs[kk][n0 + 4];
            #pragma unroll
            for (int mi = 0; mi < 8; mi++)
                #pragma unroll
                for (int ni = 0; ni < 8; ni++)
                    acc[mi][ni] = fmaf(a[mi], b[ni], acc[mi][ni]);
        }
    }

    // Scatter epilogue: out[(bt*C + c_out)*4096 + rem]
    const int bt = rowBase >> 12;
    #pragma unroll
    for (int mi = 0; mi < 8; mi++) {
        const int r   = rowBase + m0 + mi;
        const int rem = r & 4095;
        #pragma unroll
        for (int ni = 0; ni < 8; ni++) {
            const int c_out = colBase + n0 + ni;
            out[((size_t)(bt * C_ + c_out) << 12) + rem] = acc[mi][ni] + bias[c_out];
        }
    }
}

// ---------------------------------------------------------------------------
extern "C" void kernel_launch(void* const* d_in, const int* in_sizes, int n_in,
                              void* d_out, int out_size)
{
    const float* x      = (const float*)d_in[0];
    const float* rb     = (const float*)d_in[1];
    const float* w_qkv  = (const float*)d_in[2];
    const float* b_qkv  = (const float*)d_in[3];
    const float* w_proj = (const float*)d_in[4];
    const float* b_proj = (const float*)d_in[5];
    float* out = (float*)d_out;
    (void)in_sizes; (void)n_in; (void)out_size;

    qkv_kernel<<<dim3(NTOK / BM, 768 / BN), 256>>>(x, w_qkv, b_qkv);
    attn_kernel<<<dim3(NSEQ, HEADS / 2), 128>>>(rb);
    proj_kernel<<<dim3(NTOK / BM, C_ / BN), 256>>>(w_proj, b_proj, out);
}

// round 13
// speedup vs baseline: 1.1467x; 1.1467x over previous
#include <cuda_runtime.h>

// Problem constants
#define B_    4
#define T_    16
#define C_    256
#define H_    64
#define W_    64
#define HEADS 8
#define DH    32          // head dim
#define NSEQ  (B_*T_*H_)  // 4096 sequences of length W_=64
#define NTOK  (NSEQ*W_)   // 262144 tokens
#define SCALE 0.17677669529663689f  // 1/sqrt(32)

// Scratch: the exact R5 footprint that passed (delta 0).
// g_q is reused for the attention output (each thread consumes its own q row
// into registers before overwriting it; k/v are read via SMEM copies).
__device__ float g_q[(size_t)NTOK * C_];
__device__ float g_k[(size_t)NTOK * C_];
__device__ float g_v[(size_t)NTOK * C_];

// ---------------------------------------------------------------------------
// GEMM tiling: BM=BN=128, BK=16, 256 threads, 8x8 micro-tile, double-buffered
// SMEM (one __syncthreads per k-tile; global loads for tile kt+1 overlap the
// compute of tile kt). Row stride 132 floats keeps transposed stores (proj A)
// at worst 2-way conflicted and float4-aligned.
// ---------------------------------------------------------------------------
#define BKK 16
#define AST 132

// ---------------------------------------------------------------------------
// Kernel 1: fused gather + QKV GEMM.
//   A[r, c] = x[bt, c, rem],  r = bt*4096 + rem  (contiguous in r per c)
//   qkv[r, j] = sum_c A[r,c] * w_qkv[c, j] + b_qkv[j]   -> g_q/g_k/g_v
// ---------------------------------------------------------------------------
__global__ __launch_bounds__(256) void qkv_kernel(
    const float* __restrict__ x,
    const float* __restrict__ w,      // [256, 768]
    const float* __restrict__ bias)   // [768]
{
    __shared__ float As[2][BKK][AST];
    __shared__ float Bs[2][BKK][AST];

    const int tid     = threadIdx.x;
    const int rowBase = blockIdx.x * 128;
    const int colBase = blockIdx.y * 128;

    const int bt   = rowBase >> 12;
    const int rem0 = rowBase & 4095;

    // Load mappings (512 float4 per matrix per tile; 2 per thread)
    const int a_c  = tid >> 5;             // 0..7  (second pass: +8)
    const int a_m4 = (tid & 31) << 2;
    const int b_c  = tid >> 5;
    const int b_j4 = (tid & 31) << 2;

    const int ty = tid >> 4, tx = tid & 15;
    const int m0 = ty * 8,   n0 = tx * 8;

    float acc[8][8];
    #pragma unroll
    for (int mi = 0; mi < 8; mi++)
        #pragma unroll
        for (int ni = 0; ni < 8; ni++) acc[mi][ni] = 0.f;

    float4 a0, a1, b0, b1;
    // preload tile 0
    a0 = *(const float4*)(x + ((size_t)(bt * C_ + a_c)     << 12) + rem0 + a_m4);
    a1 = *(const float4*)(x + ((size_t)(bt * C_ + a_c + 8) << 12) + rem0 + a_m4);
    b0 = *(const float4*)(w + (size_t)(b_c)     * 768 + colBase + b_j4);
    b1 = *(const float4*)(w + (size_t)(b_c + 8) * 768 + colBase + b_j4);
    *(float4*)&As[0][a_c][a_m4]     = a0;
    *(float4*)&As[0][a_c + 8][a_m4] = a1;
    *(float4*)&Bs[0][b_c][b_j4]     = b0;
    *(float4*)&Bs[0][b_c + 8][b_j4] = b1;
    __syncthreads();

    const int NT = C_ / BKK;   // 16
    for (int kt = 0; kt < NT; kt++) {
        const int buf = kt & 1;
        if (kt + 1 < NT) {
            const int kc = (kt + 1) * BKK;
            a0 = *(const float4*)(x + ((size_t)(bt * C_ + kc + a_c)     << 12) + rem0 + a_m4);
            a1 = *(const float4*)(x + ((size_t)(bt * C_ + kc + a_c + 8) << 12) + rem0 + a_m4);
            b0 = *(const float4*)(w + (size_t)(kc + b_c)     * 768 + colBase + b_j4);
            b1 = *(const float4*)(w + (size_t)(kc + b_c + 8) * 768 + colBase + b_j4);
        }
        #pragma unroll
        for (int kk = 0; kk < BKK; kk++) {
            float a[8], b[8];
            *(float4*)&a[0] = *(const float4*)&As[buf][kk][m0];
            *(float4*)&a[4] = *(const float4*)&As[buf][kk][m0 + 4];
            *(float4*)&b[0] = *(const float4*)&Bs[buf][kk][n0];
            *(float4*)&b[4] = *(const float4*)&Bs[buf][kk][n0 + 4];
            #pragma unroll
            for (int mi = 0; mi < 8; mi++)
                #pragma unroll
                for (int ni = 0; ni < 8; ni++)
                    acc[mi][ni] = fmaf(a[mi], b[ni], acc[mi][ni]);
        }
        if (kt + 1 < NT) {
            const int nb = buf ^ 1;
            *(float4*)&As[nb][a_c][a_m4]     = a0;
            *(float4*)&As[nb][a_c + 8][a_m4] = a1;
            *(float4*)&Bs[nb][b_c][b_j4]     = b0;
            *(float4*)&Bs[nb][b_c + 8][b_j4] = b1;
            __syncthreads();
        }
    }

    // Epilogue: route to q/k/v (tile fully in one part since 128 | 256)
    const int part = colBase >> 8;                  // 0=q, 1=k, 2=v
    float* dst = (part == 0) ? g_q : (part == 1) ? g_k : g_v;
    const int jl0 = (colBase & 255) + n0;

    #pragma unroll
    for (int mi = 0; mi < 8; mi++) {
        const size_t rofs = (size_t)(rowBase + m0 + mi) * C_;
        #pragma unroll
        for (int ni = 0; ni < 8; ni++) {
            dst[rofs + jl0 + ni] = acc[mi][ni] + bias[colBase + n0 + ni];
        }
    }
}

// ---------------------------------------------------------------------------
// Kernel 2: attention per (sequence, head-pair) — byte-identical to the
// passing R5 kernel. k/v in SMEM, q/scores/output register-resident,
// o overwrites g_q in place.
// ---------------------------------------------------------------------------
__global__ __launch_bounds__(128) void attn_kernel(const float* __restrict__ rb)
{
    __shared__ float ksm[2 * 64 * DH];
    __shared__ float vsm[2 * 64 * DH];

    const int tid  = threadIdx.x;
    const int n    = blockIdx.x;
    const int hp   = blockIdx.y;
    const int hsub = tid >> 6;
    const int i    = tid & 63;
    const int h    = hp * 2 + hsub;

    const size_t base = (size_t)n * 64 * C_;

    #pragma unroll
    for (int it = 0; it < 8; it++) {
        int e   = tid + 128 * it;
        int hs  = e >> 9;
        int row = (e >> 3) & 63;
        int d4  = (e & 7) << 2;
        int hh  = hp * 2 + hs;
        size_t g = base + (size_t)row * C_ + hh * DH + d4;
        ((float4*)ksm)[e] = *(const float4*)&g_k[g];
        ((float4*)vsm)[e] = *(const float4*)&g_v[g];
    }

    float qv[DH];
    const size_t qbase = base + (size_t)i * C_ + h * DH;
    #pragma unroll
    for (int d = 0; d < DH; d += 4) {
        float4 t = *(const float4*)&g_q[qbase + d];
        qv[d] = t.x; qv[d+1] = t.y; qv[d+2] = t.z; qv[d+3] = t.w;
    }
    __syncthreads();

    const float* brow  = rb + (size_t)h * 4096 + i * 64;
    const float* kbase = ksm + hsub * (64 * DH);
    float s[64];
    float m = -1e30f;
    #pragma unroll
    for (int j = 0; j < 64; j++) {
        const float* krow = kbase + j * DH;
        float d0 = 0.f, d1 = 0.f, d2 = 0.f, d3 = 0.f;
        #pragma unroll
        for (int d = 0; d < DH; d += 4) {
            float4 kvv = *(const float4*)&krow[d];
            d0 = fmaf(qv[d],   kvv.x, d0);
            d1 = fmaf(qv[d+1], kvv.y, d1);
            d2 = fmaf(qv[d+2], kvv.z, d2);
            d3 = fmaf(qv[d+3], kvv.w, d3);
        }
        float sc = fmaf((d0 + d1) + (d2 + d3), SCALE, brow[j]);
        s[j] = sc;
        m = fmaxf(m, sc);
    }

    float sum = 0.f;
    #pragma unroll
    for (int j = 0; j < 64; j++) {
        float e = __expf(s[j] - m);
        s[j] = e;
        sum += e;
    }
    const float inv = 1.f / sum;

    float o[DH];
    #pragma unroll
    for (int d = 0; d < DH; d++) o[d] = 0.f;
    const float* vbase = vsm + hsub * (64 * DH);
    #pragma unroll
    for (int j = 0; j < 64; j++) {
        float p = s[j] * inv;
        const float* vrow = vbase + j * DH;
        #pragma unroll
        for (int d = 0; d < DH; d += 4) {
            float4 vv = *(const float4*)&vrow[d];
            o[d]   = fmaf(p, vv.x, o[d]);
            o[d+1] = fmaf(p, vv.y, o[d+1]);
            o[d+2] = fmaf(p, vv.z, o[d+2]);
            o[d+3] = fmaf(p, vv.w, o[d+3]);
        }
    }

    #pragma unroll
    for (int d = 0; d < DH; d += 4) {
        float4 t; t.x = o[d]; t.y = o[d+1]; t.z = o[d+2]; t.w = o[d+3];
        *(float4*)&g_q[qbase + d] = t;
    }
}

// ---------------------------------------------------------------------------
// Kernel 3: output projection + scatter, BK=16 double-buffered.
//   out[r, c_out] = sum_c g_q[r,c] * w_proj[c, c_out] + b_proj[c_out]
// A is row-major [NTOK, 256] -> transposed store into As (2-way conflicts
// thanks to the 132-float row stride).
// ---------------------------------------------------------------------------
__global__ __launch_bounds__(256) void proj_kernel(
    const float* __restrict__ w,      // [256, 256]
    const float* __restrict__ bias,   // [256]
    float* __restrict__ out)
{
    __shared__ float As[2][BKK][AST];
    __shared__ float Bs[2][BKK][AST];

    const int tid     = threadIdx.x;
    const int rowBase = blockIdx.x * 128;
    const int colBase = blockIdx.y * 128;

    // A: thread loads float4 along k of one row m (two rows: m, m+64)
    const int a_m  = tid >> 2;             // 0..63
    const int a_k4 = (tid & 3) << 2;       // 0,4,8,12
    // B: same as qkv
    const int b_c  = tid >> 5;
    const int b_j4 = (tid & 31) << 2;

    const int ty = tid >> 4, tx = tid & 15;
    const int m0 = ty * 8,   n0 = tx * 8;

    float acc[8][8];
    #pragma unroll
    for (int mi = 0; mi < 8; mi++)
        #pragma unroll
        for (int ni = 0; ni < 8; ni++) acc[mi][ni] = 0.f;

    float4 a0, a1, b0, b1;
    a0 = *(const float4*)(g_q + (size_t)(rowBase + a_m)      * C_ + a_k4);
    a1 = *(const float4*)(g_q + (size_t)(rowBase + a_m + 64) * C_ + a_k4);
    b0 = *(const float4*)(w + (size_t)(b_c)     * C_ + colBase + b_j4);
    b1 = *(const float4*)(w + (size_t)(b_c + 8) * C_ + colBase + b_j4);
    As[0][a_k4+0][a_m] = a0.x; As[0][a_k4+1][a_m] = a0.y;
    As[0][a_k4+2][a_m] = a0.z; As[0][a_k4+3][a_m] = a0.w;
    As[0][a_k4+0][a_m+64] = a1.x; As[0][a_k4+1][a_m+64] = a1.y;
    As[0][a_k4+2][a_m+64] = a1.z; As[0][a_k4+3][a_m+64] = a1.w;
    *(float4*)&Bs[0][b_c][b_j4]     = b0;
    *(float4*)&Bs[0][b_c + 8][b_j4] = b1;
    __syncthreads();

    const int NT = C_ / BKK;   // 16
    for (int kt = 0; kt < NT; kt++) {
        const int buf = kt & 1;
        if (kt + 1 < NT) {
            const int kc = (kt + 1) * BKK;
            a0 = *(const float4*)(g_q + (size_t)(rowBase + a_m)      * C_ + kc + a_k4);
            a1 = *(const float4*)(g_q + (size_t)(rowBase + a_m + 64) * C_ + kc + a_k4);
            b0 = *(const float4*)(w + (size_t)(kc + b_c)     * C_ + colBase + b_j4);
            b1 = *(const float4*)(w + (size_t)(kc + b_c + 8) * C_ + colBase + b_j4);
        }
        #pragma unroll
        for (int kk = 0; kk < BKK; kk++) {
            float a[8], b[8];
            *(float4*)&a[0] = *(const float4*)&As[buf][kk][m0];
            *(float4*)&a[4] = *(const float4*)&As[buf][kk][m0 + 4];
            *(float4*)&b[0] = *(const float4*)&Bs[buf][kk][n0];
            *(float4*)&b[4] = *(const float4*)&Bs[buf][kk][n0 + 4];
            #pragma unroll
            for (int mi = 0; mi < 8; mi++)
                #pragma unroll
                for (int ni = 0; ni < 8; ni++)
                    acc[mi][ni] = fmaf(a[mi], b[ni], acc[mi][ni]);
        }
        if (kt + 1 < NT) {
            const int nb = buf ^ 1;
            As[nb][a_k4+0][a_m] = a0.x; As[nb][a_k4+1][a_m] = a0.y;
            As[nb][a_k4+2][a_m] = a0.z; As[nb][a_k4+3][a_m] = a0.w;
            As[nb][a_k4+0][a_m+64] = a1.x; As[nb][a_k4+1][a_m+64] = a1.y;
            As[nb][a_k4+2][a_m+64] = a1.z; As[nb][a_k4+3][a_m+64] = a1.w;
            *(float4*)&Bs[nb][b_c][b_j4]     = b0;
            *(float4*)&Bs[nb][b_c + 8][b_j4] = b1;
            __syncthreads();
        }
    }

    // Scatter epilogue: out[(bt*C + c_out)*4096 + rem]
    const int bt = rowBase >> 12;
    #pragma unroll
    for (int mi = 0; mi < 8; mi++) {
        const int r   = rowBase + m0 + mi;
        const int rem = r & 4095;
        #pragma unroll
        for (int ni = 0; ni < 8; ni++) {
            const int c_out = colBase + n0 + ni;
            out[((size_t)(bt * C_ + c_out) << 12) + rem] = acc[mi][ni] + bias[c_out];
        }
    }
}

// ---------------------------------------------------------------------------
extern "C" void kernel_launch(void* const* d_in, const int* in_sizes, int n_in,
                              void* d_out, int out_size)
{
    const float* x      = (const float*)d_in[0];
    const float* rb     = (const float*)d_in[1];
    const float* w_qkv  = (const float*)d_in[2];
    const float* b_qkv  = (const float*)d_in[3];
    const float* w_proj = (const float*)d_in[4];
    const float* b_proj = (const float*)d_in[5];
    float* out = (float*)d_out;
    (void)in_sizes; (void)n_in; (void)out_size;

    qkv_kernel<<<dim3(NTOK / 128, 6), 256>>>(x, w_qkv, b_qkv);
    attn_kernel<<<dim3(NSEQ, HEADS / 2), 128>>>(rb);
    proj_kernel<<<dim3(NTOK / 128, 2), 256>>>(w_proj, b_proj, out);
}